// round 6
// baseline (speedup 1.0000x reference)
#include <cuda_runtime.h>

// 2-layer LSTM (H=30, IN=1) + linear head, B=512, T=2048.
// Block = 1 batch element, 256 threads = 8 warps, two specialist groups:
//   Group A (warps 0-3): L1 gates for step n  (needs h1[n-1], x[n])
//   Group B (warps 4-7): L2 gates for step n-1 (needs h1[n-1], h2[n-2]) + FC
// Quad layout: lane 4*u+g -> unit u, gate g (0=i,1=f,2=g,3=o). The 4 gates of
// a unit sit in one warp, so gate->state exchange is 4 intra-warp shfl (no
// gate SMEM buffer, no syncwarp). h1/h2/FC-partials are parity double-buffered
// in SMEM; exactly ONE __syncthreads per iteration.
// Weight rows register-resident, f32x2-packed, in ONE shared 30-ull array
// (A uses [0..14]=w_hh1 row; B uses [0..14]=w_ih2, [15..29]=w_hh2 rows).

#define Hs 30
#define Ts 2048
#define Bs 512

typedef unsigned long long ull;

__device__ __forceinline__ ull pk(float lo, float hi) {
    ull r; asm("mov.b64 %0, {%1, %2};" : "=l"(r) : "f"(lo), "f"(hi)); return r;
}
__device__ __forceinline__ void fma2(ull& d, ull a, ull b) {
    asm("fma.rn.f32x2 %0, %1, %2, %3;" : "=l"(d) : "l"(a), "l"(b), "l"(d));
}
__device__ __forceinline__ ull add2(ull a, ull b) {
    ull r; asm("add.rn.f32x2 %0, %1, %2;" : "=l"(r) : "l"(a), "l"(b)); return r;
}
__device__ __forceinline__ float hadd(ull a) {
    float lo, hi; asm("mov.b64 {%0, %1}, %2;" : "=f"(lo), "=f"(hi) : "l"(a)); return lo + hi;
}
__device__ __forceinline__ float ex2f(float x) { float y; asm("ex2.approx.f32 %0, %1;" : "=f"(y) : "f"(x)); return y; }
__device__ __forceinline__ float rcpf(float x) { float y; asm("rcp.approx.f32 %0, %1;" : "=f"(y) : "f"(x)); return y; }

// act(x) = aa * rcp(1 + ex2(bb*x)) + cc  (sigmoid or tanh by per-lane consts)
__device__ __forceinline__ float act(float x, float aa, float bb, float cc) {
    return fmaf(aa, rcpf(1.0f + ex2f(bb * x)), cc);
}
__device__ __forceinline__ float tanh_(float x) {
    return fmaf(-2.0f, rcpf(ex2f(2.8853900817779268f * x) + 1.0f), 1.0f);
}

__global__ void __launch_bounds__(256, 3) lstm_kernel(
    const float* __restrict__ x,
    const float* __restrict__ w_ih1, const float* __restrict__ w_hh1,
    const float* __restrict__ b_ih1, const float* __restrict__ b_hh1,
    const float* __restrict__ w_ih2, const float* __restrict__ w_hh2,
    const float* __restrict__ b_ih2, const float* __restrict__ b_hh2,
    const float* __restrict__ w_fc,  const float* __restrict__ b_fc,
    float* __restrict__ out)
{
    __shared__ __align__(16) float sx[Ts];       // x row for this batch element
    __shared__ __align__(16) float h1b[2][32];   // h1, parity double-buffered
    __shared__ __align__(16) float h2b[2][32];   // h2, parity double-buffered
    __shared__ __align__(16) float sp[2][4];     // FC warp partials, parity

    const int tid  = threadIdx.x;
    const int g    = tid & 3;          // gate type within quad
    const int u    = (tid >> 2) & 31;  // unit (30,31 pad)
    const int lane = tid & 31;
    const int wid  = tid >> 5;
    const int base = lane & ~3;        // quad base lane for shfl gather
    const bool isB = (tid >= 128);
    const int b    = blockIdx.x;

    {   // coalesced x preload (512 float4 over 256 threads)
        const float4* xb4 = (const float4*)(x + (size_t)b * Ts);
        float4* sx4 = (float4*)sx;
        sx4[tid]       = xb4[tid];
        sx4[tid + 256] = xb4[tid + 256];
    }
    if (tid < 32) {
        h1b[0][tid] = 0.0f; h1b[1][tid] = 0.0f;
        h2b[0][tid] = 0.0f; h2b[1][tid] = 0.0f;
    }
    if (tid < 8) ((float*)sp)[tid] = 0.0f;

    // Weight rows, f32x2 packed. One array shared by both groups (uniform
    // register allocation): A fills [0..14] with its w_hh1 row; B fills
    // [0..14] with w_ih2 and [15..29] with w_hh2.
    const int row = g * Hs + ((u < Hs) ? u : Hs - 1);
    ull wA[30];
    float k0, k1;   // A: (wx, bias1)   B: (unused, bias2)
    if (!isB) {
        const float* r1 = w_hh1 + row * Hs;
        #pragma unroll
        for (int k = 0; k < 15; k++) wA[k] = pk(r1[2 * k], r1[2 * k + 1]);
        #pragma unroll
        for (int k = 15; k < 30; k++) wA[k] = 0ull;
        k0 = w_ih1[row];
        k1 = b_ih1[row] + b_hh1[row];
    } else {
        const float* r2i = w_ih2 + row * Hs;
        const float* r2h = w_hh2 + row * Hs;
        #pragma unroll
        for (int k = 0; k < 15; k++) {
            wA[k]      = pk(r2i[2 * k], r2i[2 * k + 1]);
            wA[15 + k] = pk(r2h[2 * k], r2h[2 * k + 1]);
        }
        k0 = 0.0f;
        k1 = b_ih2[row] + b_hh2[row];
    }
    const float wfc = (isB && g == 0 && u < Hs) ? w_fc[u] : 0.0f;
    const float bfc = b_fc[0];

    // Per-lane activation constants (g==2 -> tanh; else sigmoid)
    const float aa = (g == 2) ? 2.0f : 1.0f;
    const float bb = (g == 2) ? -2.8853900817779268f : -1.4426950408889634f;
    const float cc = (g == 2) ? -1.0f : 0.0f;

    float c = 0.0f;                    // c1 for group A, c2 for group B
    float* __restrict__ outb = out + (size_t)b * Ts;

    __syncthreads();

    int pr = 0;   // parity: read buf[pr], write buf[pr^1]
    #pragma unroll 1
    for (int n = 0; n <= Ts; n++) {
        if (!isB) {
            // ---- Group A: L1 step n ----
            if (n < Ts) {
                const ulonglong2* hp = (const ulonglong2*)h1b[pr];
                ull a0 = 0ull, a1 = 0ull;
                #pragma unroll
                for (int k = 0; k < 7; k++) {
                    ulonglong2 v = hp[k];
                    fma2(a0, wA[2 * k],     v.x);
                    fma2(a1, wA[2 * k + 1], v.y);
                }
                fma2(a0, wA[14], ((const ull*)hp)[14]);
                float pre = fmaf(sx[n], k0, k1) + hadd(add2(a0, a1));
                float a = act(pre, aa, bb, cc);
                float gi = __shfl_sync(0xffffffffu, a, base);
                float gf = __shfl_sync(0xffffffffu, a, base + 1);
                float gg = __shfl_sync(0xffffffffu, a, base + 2);
                float go = __shfl_sync(0xffffffffu, a, base + 3);
                c = fmaf(gf, c, gi * gg);
                float hv = go * tanh_(c);
                if (g == 0) h1b[pr ^ 1][u] = hv;
            }
        } else {
            // ---- FC output for step n-2 (partials were written at iter n-1,
            // ordered by the barrier at the end of iter n-1) ----
            if (tid == 128 && n >= 2) {
                float4 s4 = *(const float4*)sp[pr];
                outb[n - 2] = s4.x + s4.y + s4.z + s4.w + bfc;
            }
            // ---- Group B: L2 step n-1 ----
            if (n >= 1) {
                const ulonglong2* hp1 = (const ulonglong2*)h1b[pr];
                const ulonglong2* hp2 = (const ulonglong2*)h2b[pr];
                ull e0 = 0ull, e1 = 0ull, d0 = 0ull, d1 = 0ull;
                #pragma unroll
                for (int k = 0; k < 7; k++) {
                    ulonglong2 v1 = hp1[k];
                    ulonglong2 v2 = hp2[k];
                    fma2(e0, wA[2 * k],      v1.x);
                    fma2(e1, wA[2 * k + 1],  v1.y);
                    fma2(d0, wA[15 + 2 * k], v2.x);
                    fma2(d1, wA[16 + 2 * k], v2.y);
                }
                fma2(e0, wA[14], ((const ull*)hp1)[14]);
                fma2(d0, wA[29], ((const ull*)hp2)[14]);
                float pre = k1 + hadd(add2(add2(e0, e1), add2(d0, d1)));
                float a = act(pre, aa, bb, cc);
                float gi = __shfl_sync(0xffffffffu, a, base);
                float gf = __shfl_sync(0xffffffffu, a, base + 1);
                float gg = __shfl_sync(0xffffffffu, a, base + 2);
                float go = __shfl_sync(0xffffffffu, a, base + 3);
                c = fmaf(gf, c, gi * gg);
                float hv = go * tanh_(c);
                if (g == 0) h2b[pr ^ 1][u] = hv;
                // FC partial over this warp's 8 units (g==0 lanes carry value)
                float p = wfc * hv;
                #pragma unroll
                for (int s = 16; s; s >>= 1) p += __shfl_xor_sync(0xffffffffu, p, s);
                if (lane == 0) sp[pr ^ 1][wid - 4] = p;
            }
        }
        __syncthreads();
        pr ^= 1;
    }

    // Final output: partials for step Ts-1 written at iter Ts (buf pr after flip)
    if (tid == 128) {
        float4 s4 = *(const float4*)sp[pr];
        outb[Ts - 1] = s4.x + s4.y + s4.z + s4.w + bfc;
    }
}

extern "C" void kernel_launch(void* const* d_in, const int* in_sizes, int n_in,
                              void* d_out, int out_size) {
    (void)in_sizes; (void)n_in; (void)out_size;
    lstm_kernel<<<Bs, 256>>>(
        (const float*)d_in[0],
        (const float*)d_in[1], (const float*)d_in[2],
        (const float*)d_in[3], (const float*)d_in[4],
        (const float*)d_in[5], (const float*)d_in[6],
        (const float*)d_in[7], (const float*)d_in[8],
        (const float*)d_in[9], (const float*)d_in[10],
        (float*)d_out);
}

// round 7
// speedup vs baseline: 5.7411x; 5.7411x over previous
#include <cuda_runtime.h>

// 2-layer LSTM (H=30, IN=1) + linear head, B=512, T=2048.
// Block = 1 batch element, 128 threads = 4 warps, QUAD layout:
//   thread tid -> gate g = tid&3 (0=i,1=f,2=g,3=o), unit u = tid>>2 (30,31 pad)
// Each thread owns unit u / gate g for BOTH layers: w_hh1, w_ih2, w_hh2 rows
// register-resident (15 f32x2 each = 90 regs). Iteration n computes L1 step n
// and L2 step n-1 fused (both need only h1[n-1], h2[n-2]); the a- and e-dots
// share the same h1 loads. Gate->state exchange = 4 intra-warp shfl (all 4
// gates of a unit live in one quad). ONE __syncthreads per iteration; h1/h2
// parity double-buffered. FC head: butterfly partials -> sp, emitted by a pad
// lane two iterations later.

#define Hs 30
#define Ts 2048
#define Bs 512

typedef unsigned long long ull;

__device__ __forceinline__ ull pk(float lo, float hi) {
    ull r; asm("mov.b64 %0, {%1, %2};" : "=l"(r) : "f"(lo), "f"(hi)); return r;
}
__device__ __forceinline__ void fma2(ull& d, ull a, ull b) {
    asm("fma.rn.f32x2 %0, %1, %2, %3;" : "=l"(d) : "l"(a), "l"(b), "l"(d));
}
__device__ __forceinline__ ull add2(ull a, ull b) {
    ull r; asm("add.rn.f32x2 %0, %1, %2;" : "=l"(r) : "l"(a), "l"(b)); return r;
}
__device__ __forceinline__ float hadd(ull a) {
    float lo, hi; asm("mov.b64 {%0, %1}, %2;" : "=f"(lo), "=f"(hi) : "l"(a)); return lo + hi;
}
__device__ __forceinline__ float ex2f(float x) { float y; asm("ex2.approx.f32 %0, %1;" : "=f"(y) : "f"(x)); return y; }
__device__ __forceinline__ float rcpf(float x) { float y; asm("rcp.approx.f32 %0, %1;" : "=f"(y) : "f"(x)); return y; }

__device__ __forceinline__ float act(float x, float aa, float bb, float cc) {
    return fmaf(aa, rcpf(1.0f + ex2f(bb * x)), cc);
}
__device__ __forceinline__ float tanh_(float x) {
    return fmaf(-2.0f, rcpf(ex2f(2.8853900817779268f * x) + 1.0f), 1.0f);
}

__global__ void __launch_bounds__(128, 4) lstm_kernel(
    const float* __restrict__ x,
    const float* __restrict__ w_ih1, const float* __restrict__ w_hh1,
    const float* __restrict__ b_ih1, const float* __restrict__ b_hh1,
    const float* __restrict__ w_ih2, const float* __restrict__ w_hh2,
    const float* __restrict__ b_ih2, const float* __restrict__ b_hh2,
    const float* __restrict__ w_fc,  const float* __restrict__ b_fc,
    float* __restrict__ out)
{
    __shared__ __align__(16) float sx[Ts];      // x row for this batch element
    __shared__ __align__(16) float h1b[2][32];  // h1, parity double-buffered
    __shared__ __align__(16) float h2b[2][32];  // h2, parity double-buffered
    __shared__ __align__(16) float sp[2][4];    // FC warp partials, parity

    const int tid  = threadIdx.x;
    const int g    = tid & 3;          // gate type (0=i,1=f,2=g,3=o)
    const int u    = tid >> 2;         // unit (30,31 pad)
    const int lane = tid & 31;
    const int wid  = tid >> 5;
    const int base = lane & ~3;        // quad base lane
    const int b    = blockIdx.x;

    {   // coalesced x preload
        const float4* xb4 = (const float4*)(x + (size_t)b * Ts);
        float4* sx4 = (float4*)sx;
        #pragma unroll
        for (int i = 0; i < Ts / 4 / 128; i++) sx4[tid + i * 128] = xb4[tid + i * 128];
    }
    if (tid < 32) {
        h1b[0][tid] = 0.0f; h1b[1][tid] = 0.0f;
        h2b[0][tid] = 0.0f; h2b[1][tid] = 0.0f;
    }
    if (tid < 8) ((float*)sp)[tid] = 0.0f;

    // Register-resident weight rows for (gate g, unit u), f32x2 packed.
    const int row = g * Hs + ((u < Hs) ? u : Hs - 1);
    ull w1p[15], w2i[15], w2h[15];
    {
        const float* r1  = w_hh1 + row * Hs;
        const float* r2i = w_ih2 + row * Hs;
        const float* r2h = w_hh2 + row * Hs;
        #pragma unroll
        for (int k = 0; k < 15; k++) {
            w1p[k] = pk(r1[2 * k],  r1[2 * k + 1]);
            w2i[k] = pk(r2i[2 * k], r2i[2 * k + 1]);
            w2h[k] = pk(r2h[2 * k], r2h[2 * k + 1]);
        }
    }
    const float k0  = w_ih1[row];
    const float b1  = b_ih1[row] + b_hh1[row];
    const float b2  = b_ih2[row] + b_hh2[row];
    const float wfc = (g == 0 && u < Hs) ? w_fc[u] : 0.0f;
    const float bfc = b_fc[0];

    // Per-lane activation constants (g==2 -> tanh, else sigmoid)
    const float aa = (g == 2) ? 2.0f : 1.0f;
    const float bb = (g == 2) ? -2.8853900817779268f : -1.4426950408889634f;
    const float cc = (g == 2) ? -1.0f : 0.0f;

    float c1 = 0.0f, c2 = 0.0f;
    float* __restrict__ outb = out + (size_t)b * Ts;

    __syncthreads();

    // ---- Peeled n = 0: L1 step 0 only (h1[-1] = 0, dot vanishes) ----
    {
        float a = act(fmaf(sx[0], k0, b1), aa, bb, cc);
        float gi = __shfl_sync(0xffffffffu, a, base);
        float gf = __shfl_sync(0xffffffffu, a, base + 1);
        float gg = __shfl_sync(0xffffffffu, a, base + 2);
        float go = __shfl_sync(0xffffffffu, a, base + 3);
        c1 = gi * gg;  (void)gf;
        float h1v = go * tanh_(c1);
        if (g == 0) h1b[1][u] = h1v;
        __syncthreads();
    }

    int pr = 1;   // read buf[pr], write buf[pr^1]
    #pragma unroll 1
    for (int n = 1; n < Ts; n++) {
        // Emit FC output for step n-2 (partials written at iter n-1).
        if (tid == 127 && n >= 2) {
            float4 s4 = *(const float4*)sp[pr];
            outb[n - 2] = s4.x + s4.y + s4.z + s4.w + bfc;
        }

        // ---- Fused dots: a = w1.h1[n-1], e = w2i.h1[n-1], d = w2h.h2[n-2] ----
        const ulonglong2* hp1 = (const ulonglong2*)h1b[pr];
        const ulonglong2* hp2 = (const ulonglong2*)h2b[pr];
        ull a0 = 0ull, a1 = 0ull, e0 = 0ull, e1 = 0ull, d0 = 0ull, d1 = 0ull;
        #pragma unroll
        for (int k = 0; k < 7; k++) {
            ulonglong2 v1 = hp1[k];
            ulonglong2 v2 = hp2[k];
            fma2(a0, w1p[2 * k],     v1.x);
            fma2(a1, w1p[2 * k + 1], v1.y);
            fma2(e0, w2i[2 * k],     v1.x);
            fma2(e1, w2i[2 * k + 1], v1.y);
            fma2(d0, w2h[2 * k],     v2.x);
            fma2(d1, w2h[2 * k + 1], v2.y);
        }
        {
            ull v1t = ((const ull*)hp1)[14], v2t = ((const ull*)hp2)[14];
            fma2(a0, w1p[14], v1t);
            fma2(e0, w2i[14], v1t);
            fma2(d0, w2h[14], v2t);
        }

        float pre1 = fmaf(sx[n], k0, b1) + hadd(add2(a0, a1));
        float pre2 = b2 + hadd(add2(add2(e0, e1), add2(d0, d1)));
        float av = act(pre1, aa, bb, cc);
        float zv = act(pre2, aa, bb, cc);

        // ---- L1 state (step n) via quad shfl ----
        {
            float gi = __shfl_sync(0xffffffffu, av, base);
            float gf = __shfl_sync(0xffffffffu, av, base + 1);
            float gg = __shfl_sync(0xffffffffu, av, base + 2);
            float go = __shfl_sync(0xffffffffu, av, base + 3);
            c1 = fmaf(gf, c1, gi * gg);
            float h1v = go * tanh_(c1);
            if (g == 0) h1b[pr ^ 1][u] = h1v;
        }
        // ---- L2 state (step n-1) via quad shfl + FC partial ----
        {
            float qi = __shfl_sync(0xffffffffu, zv, base);
            float qf = __shfl_sync(0xffffffffu, zv, base + 1);
            float qg = __shfl_sync(0xffffffffu, zv, base + 2);
            float qo = __shfl_sync(0xffffffffu, zv, base + 3);
            c2 = fmaf(qf, c2, qi * qg);
            float h2v = qo * tanh_(c2);
            if (g == 0) h2b[pr ^ 1][u] = h2v;
            float p = wfc * h2v;   // nonzero only on g==0, u<30 lanes
            #pragma unroll
            for (int s = 16; s; s >>= 1) p += __shfl_xor_sync(0xffffffffu, p, s);
            if (lane == 0) sp[pr ^ 1][wid] = p;
        }
        __syncthreads();
        pr ^= 1;
    }

    // ---- Epilogue n = Ts: L2 step Ts-1 only ----
    {
        if (tid == 127) {
            float4 s4 = *(const float4*)sp[pr];
            outb[Ts - 2] = s4.x + s4.y + s4.z + s4.w + bfc;
        }
        const ulonglong2* hp1 = (const ulonglong2*)h1b[pr];
        const ulonglong2* hp2 = (const ulonglong2*)h2b[pr];
        ull e0 = 0ull, e1 = 0ull, d0 = 0ull, d1 = 0ull;
        #pragma unroll
        for (int k = 0; k < 7; k++) {
            ulonglong2 v1 = hp1[k];
            ulonglong2 v2 = hp2[k];
            fma2(e0, w2i[2 * k],     v1.x);
            fma2(e1, w2i[2 * k + 1], v1.y);
            fma2(d0, w2h[2 * k],     v2.x);
            fma2(d1, w2h[2 * k + 1], v2.y);
        }
        fma2(e0, w2i[14], ((const ull*)hp1)[14]);
        fma2(d0, w2h[14], ((const ull*)hp2)[14]);
        float zv = act(b2 + hadd(add2(add2(e0, e1), add2(d0, d1))), aa, bb, cc);
        float qi = __shfl_sync(0xffffffffu, zv, base);
        float qf = __shfl_sync(0xffffffffu, zv, base + 1);
        float qg = __shfl_sync(0xffffffffu, zv, base + 2);
        float qo = __shfl_sync(0xffffffffu, zv, base + 3);
        c2 = fmaf(qf, c2, qi * qg);
        float h2v = qo * tanh_(c2);
        float p = wfc * h2v;
        #pragma unroll
        for (int s = 16; s; s >>= 1) p += __shfl_xor_sync(0xffffffffu, p, s);
        if (lane == 0) sp[pr ^ 1][wid] = p;
        __syncthreads();
        if (tid == 127) {
            float4 s4 = *(const float4*)sp[pr ^ 1];
            outb[Ts - 1] = s4.x + s4.y + s4.z + s4.w + bfc;
        }
    }
}

extern "C" void kernel_launch(void* const* d_in, const int* in_sizes, int n_in,
                              void* d_out, int out_size) {
    (void)in_sizes; (void)n_in; (void)out_size;
    lstm_kernel<<<Bs, 128>>>(
        (const float*)d_in[0],
        (const float*)d_in[1], (const float*)d_in[2],
        (const float*)d_in[3], (const float*)d_in[4],
        (const float*)d_in[5], (const float*)d_in[6],
        (const float*)d_in[7], (const float*)d_in[8],
        (const float*)d_in[9], (const float*)d_in[10],
        (float*)d_out);
}